// round 15
// baseline (speedup 1.0000x reference)
#include <cuda_runtime.h>
#include <cuda_bf16.h>
#include <cuda_fp16.h>
#include <math.h>

#define NMAX 50048
#define EMAX 800000
#define SCAN_B 256

// ---------------- scratch (device globals) ----------------
__device__ __half2 g_h[NMAX * 64];     // x @ W_gat (fp16 messages)
__device__ __half2 g_h2[NMAX * 64];    // out1 @ W_gcn (fp16 messages)
__device__ float g_asrc[NMAX * 4];
__device__ float g_adst[NMAX * 4];
__device__ float g_out1[NMAX * 128];
__device__ float g_dinv[NMAX];
__device__ int   g_cnt[NMAX];
__device__ int   g_offs[NMAX + 1];
__device__ int   g_cursor[NMAX];
__device__ int   g_csr[EMAX];
__device__ int   g_bsum[(NMAX + SCAN_B - 1) / SCAN_B];
__device__ int   g_boff[(NMAX + SCAN_B - 1) / SCAN_B];
__device__ float g_gacc[64 * 128];
__device__ float g_gsum[64];
// packed bf16 hi/lo weights, fragment order: [slab8][col128][kq4] uint2
__device__ uint2 g_wh1[4096];
__device__ uint2 g_wl1[4096];
__device__ uint2 g_wh2[4096];
__device__ uint2 g_wl2[4096];

// ---------------- helpers ----------------
__device__ __forceinline__ float lrelu(float v) { return v > 0.f ? v : 0.2f * v; }
__device__ __forceinline__ float elu_f(float v) { return v > 0.f ? v : (__expf(v) - 1.f); }

__device__ __forceinline__ void split_bf(float x, float y, unsigned& hi, unsigned& lo) {
    __nv_bfloat162 h = __floats2bfloat162_rn(x, y);
    float rx = x - __bfloat162float(h.x);
    float ry = y - __bfloat162float(h.y);
    __nv_bfloat162 l = __floats2bfloat162_rn(rx, ry);
    hi = *(unsigned*)&h;
    lo = *(unsigned*)&l;
}

__device__ __forceinline__ void mma_bf16(float* d, const unsigned* a, unsigned b0, unsigned b1) {
    asm("mma.sync.aligned.m16n8k16.row.col.f32.bf16.bf16.f32 "
        "{%0,%1,%2,%3},{%4,%5,%6,%7},{%8,%9},{%0,%1,%2,%3};"
        : "+f"(d[0]), "+f"(d[1]), "+f"(d[2]), "+f"(d[3])
        : "r"(a[0]), "r"(a[1]), "r"(a[2]), "r"(a[3]), "r"(b0), "r"(b1));
}

// ---------------- init ----------------
__global__ void init_kernel(int* cnt, float* gacc, float* gsum, int N) {
    int i = blockIdx.x * blockDim.x + threadIdx.x;
    if (i < N) cnt[i] = 0;
    if (i < 64 * 128) gacc[i] = 0.f;
    if (i < 64) gsum[i] = 0.f;
}

// ---------------- CSR: histogram ----------------
__global__ void hist_kernel(const int* __restrict__ ei, int E, int* cnt) {
    int e = blockIdx.x * blockDim.x + threadIdx.x;
    if (e >= E) return;
    atomicAdd(cnt + ei[E + e], 1);
}

// ---------------- pack BOTH weight matrices into bf16 hi/lo fragment order ----------------
__global__ void wpack_kernel(const float* __restrict__ W1, const float* __restrict__ W2,
                             uint2* Wh1, uint2* Wl1, uint2* Wh2, uint2* Wl2) {
    int t = blockIdx.x * blockDim.x + threadIdx.x;
    if (t >= 8192) return;
    const float* W = (t < 4096) ? W1 : W2;
    uint2* Wh = (t < 4096) ? Wh1 : Wh2;
    uint2* Wl = (t < 4096) ? Wl1 : Wl2;
    int i = t & 4095;
    int kq   = i & 3;
    int col  = (i >> 2) & 127;
    int slab = i >> 9;
    int k0 = slab * 16 + 2 * kq;
    uint2 h, l;
    split_bf(W[k0 * 128 + col],       W[(k0 + 1) * 128 + col], h.x, l.x);
    split_bf(W[(k0 + 8) * 128 + col], W[(k0 + 9) * 128 + col], h.y, l.y);
    Wh[i] = h;
    Wl[i] = l;
}

// ---------------- tensor-core GEMM: Ch[N,128](fp16) = A[N,128] @ W[128,128], 3xBF16 ----------------
template <bool ATTN>
__global__ __launch_bounds__(256, 2) void gemm_tc_kernel(const float* __restrict__ A,
                                                         const uint2* __restrict__ Wh,
                                                         const uint2* __restrict__ Wl,
                                                         __half2* __restrict__ Ch,
                                                         const float* __restrict__ att_src,
                                                         const float* __restrict__ att_dst,
                                                         float* __restrict__ asrc,
                                                         float* __restrict__ adst, int N) {
    __shared__ float As[2][64 * 36];
    __shared__ uint2 Bh[2][1024];
    __shared__ uint2 Bl[2][1024];

    int t = threadIdx.x;
    int warp = t >> 5, lane = t & 31;
    int g4 = lane >> 2, kq = lane & 3;
    int rg = warp >> 1;
    int ch = warp & 1;
    int wrow = rg * 16;
    int brow0 = blockIdx.x * 64;

    int arow0 = t >> 3, ac4 = t & 7;
    int arow1 = (t + 256) >> 3;

    float acc[8][4];
    #pragma unroll
    for (int j = 0; j < 8; j++)
        #pragma unroll
        for (int q = 0; q < 4; q++) acc[j][q] = 0.f;

    {
        float4 va0 = make_float4(0.f, 0.f, 0.f, 0.f);
        float4 va1 = make_float4(0.f, 0.f, 0.f, 0.f);
        if (brow0 + arow0 < N) va0 = ((const float4*)A)[(brow0 + arow0) * 32 + ac4];
        if (brow0 + arow1 < N) va1 = ((const float4*)A)[(brow0 + arow1) * 32 + ac4];
        float4 vh0 = ((const float4*)Wh)[t];
        float4 vh1 = ((const float4*)Wh)[t + 256];
        float4 vl0 = ((const float4*)Wl)[t];
        float4 vl1 = ((const float4*)Wl)[t + 256];
        *(float4*)(As[0] + arow0 * 36 + ac4 * 4) = va0;
        *(float4*)(As[0] + arow1 * 36 + ac4 * 4) = va1;
        ((float4*)Bh[0])[t] = vh0;
        ((float4*)Bh[0])[t + 256] = vh1;
        ((float4*)Bl[0])[t] = vl0;
        ((float4*)Bl[0])[t + 256] = vl1;
    }
    __syncthreads();

    #pragma unroll
    for (int stage = 0; stage < 4; stage++) {
        int cur = stage & 1, nxt = cur ^ 1;

        float4 va0, va1, vh0, vh1, vl0, vl1;
        if (stage < 3) {
            int s1 = stage + 1;
            va0 = make_float4(0.f, 0.f, 0.f, 0.f);
            va1 = make_float4(0.f, 0.f, 0.f, 0.f);
            if (brow0 + arow0 < N) va0 = ((const float4*)A)[(brow0 + arow0) * 32 + s1 * 8 + ac4];
            if (brow0 + arow1 < N) va1 = ((const float4*)A)[(brow0 + arow1) * 32 + s1 * 8 + ac4];
            vh0 = ((const float4*)Wh)[s1 * 512 + t];
            vh1 = ((const float4*)Wh)[s1 * 512 + t + 256];
            vl0 = ((const float4*)Wl)[s1 * 512 + t];
            vl1 = ((const float4*)Wl)[s1 * 512 + t + 256];
        }

        #pragma unroll
        for (int sl = 0; sl < 2; sl++) {
            int kb = sl * 16 + 2 * kq;
            float2 A0 = *(const float2*)(As[cur] + (wrow + g4) * 36 + kb);
            float2 A1 = *(const float2*)(As[cur] + (wrow + g4) * 36 + kb + 8);
            float2 A2 = *(const float2*)(As[cur] + (wrow + g4 + 8) * 36 + kb);
            float2 A3 = *(const float2*)(As[cur] + (wrow + g4 + 8) * 36 + kb + 8);
            unsigned ah[4], al[4];
            split_bf(A0.x, A0.y, ah[0], al[0]);
            split_bf(A2.x, A2.y, ah[1], al[1]);
            split_bf(A1.x, A1.y, ah[2], al[2]);
            split_bf(A3.x, A3.y, ah[3], al[3]);
            #pragma unroll
            for (int j = 0; j < 8; j++) {
                int ct = ch * 8 + j;
                uint2 bh = Bh[cur][sl * 512 + (ct * 8 + g4) * 4 + kq];
                uint2 bl = Bl[cur][sl * 512 + (ct * 8 + g4) * 4 + kq];
                mma_bf16(acc[j], ah, bh.x, bh.y);
                mma_bf16(acc[j], al, bh.x, bh.y);
                mma_bf16(acc[j], ah, bl.x, bl.y);
            }
        }

        if (stage < 3) {
            *(float4*)(As[nxt] + arow0 * 36 + ac4 * 4) = va0;
            *(float4*)(As[nxt] + arow1 * 36 + ac4 * 4) = va1;
            ((float4*)Bh[nxt])[t] = vh0;
            ((float4*)Bh[nxt])[t + 256] = vh1;
            ((float4*)Bl[nxt])[t] = vl0;
            ((float4*)Bl[nxt])[t + 256] = vl1;
            __syncthreads();
        }
    }

    int r0 = brow0 + wrow + g4;
    #pragma unroll
    for (int j = 0; j < 8; j++) {
        int hcol = ch * 32 + j * 4 + kq;
        if (r0 < N)
            Ch[r0 * 64 + hcol] = __floats2half2_rn(acc[j][0], acc[j][1]);
        if (r0 + 8 < N)
            Ch[(r0 + 8) * 64 + hcol] = __floats2half2_rn(acc[j][2], acc[j][3]);
    }

    if (ATTN) {
        #pragma unroll
        for (int hh = 0; hh < 2; hh++) {
            int head = ch * 2 + hh;
            float psl = 0.f, psh = 0.f, pdl = 0.f, pdh = 0.f;
            #pragma unroll
            for (int jj = 0; jj < 4; jj++) {
                int j = hh * 4 + jj;
                int col = ch * 64 + j * 8 + 2 * kq;
                float2 av = *(const float2*)(att_src + col);
                float2 dv = *(const float2*)(att_dst + col);
                psl += acc[j][0] * av.x + acc[j][1] * av.y;
                psh += acc[j][2] * av.x + acc[j][3] * av.y;
                pdl += acc[j][0] * dv.x + acc[j][1] * dv.y;
                pdh += acc[j][2] * dv.x + acc[j][3] * dv.y;
            }
            psl += __shfl_xor_sync(0xffffffffu, psl, 1);
            psl += __shfl_xor_sync(0xffffffffu, psl, 2);
            psh += __shfl_xor_sync(0xffffffffu, psh, 1);
            psh += __shfl_xor_sync(0xffffffffu, psh, 2);
            pdl += __shfl_xor_sync(0xffffffffu, pdl, 1);
            pdl += __shfl_xor_sync(0xffffffffu, pdl, 2);
            pdh += __shfl_xor_sync(0xffffffffu, pdh, 1);
            pdh += __shfl_xor_sync(0xffffffffu, pdh, 2);
            if (kq == 0) {
                if (r0 < N)     { asrc[r0 * 4 + head] = psl;       adst[r0 * 4 + head] = pdl; }
                if (r0 + 8 < N) { asrc[(r0 + 8) * 4 + head] = psh; adst[(r0 + 8) * 4 + head] = pdh; }
            }
        }
    }
}

// ---------------- CSR scan ----------------
__global__ __launch_bounds__(SCAN_B) void blocksum_kernel(const int* __restrict__ cnt,
                                                          int* bsum, int N) {
    __shared__ int sh[SCAN_B];
    int i = blockIdx.x * SCAN_B + threadIdx.x;
    sh[threadIdx.x] = (i < N) ? cnt[i] : 0;
    __syncthreads();
    #pragma unroll
    for (int o = SCAN_B / 2; o; o >>= 1) {
        if (threadIdx.x < o) sh[threadIdx.x] += sh[threadIdx.x + o];
        __syncthreads();
    }
    if (threadIdx.x == 0) bsum[blockIdx.x] = sh[0];
}

__global__ __launch_bounds__(256) void bscan_kernel(const int* __restrict__ bsum,
                                                    int* boff, int NB) {
    __shared__ int sh[256];
    int t = threadIdx.x;
    sh[t] = (t < NB) ? bsum[t] : 0;
    __syncthreads();
    #pragma unroll
    for (int o = 1; o < 256; o <<= 1) {
        int v = (t >= o) ? sh[t - o] : 0;
        __syncthreads();
        sh[t] += v;
        __syncthreads();
    }
    if (t < NB) boff[t] = (t == 0) ? 0 : sh[t - 1];
}

// scanfin also emits dinv (deg = cnt + 1 self loop)
__global__ __launch_bounds__(SCAN_B) void scanfin_kernel(const int* __restrict__ cnt,
                                                         const int* __restrict__ boff,
                                                         int* offs, int* cursor,
                                                         float* dinv, int N, int E) {
    __shared__ int sh[SCAN_B];
    int t = threadIdx.x;
    int i = blockIdx.x * SCAN_B + t;
    int v = (i < N) ? cnt[i] : 0;
    sh[t] = v;
    __syncthreads();
    #pragma unroll
    for (int o = 1; o < SCAN_B; o <<= 1) {
        int u = (t >= o) ? sh[t - o] : 0;
        __syncthreads();
        sh[t] += u;
        __syncthreads();
    }
    if (i < N) {
        int off = boff[blockIdx.x] + sh[t] - v;
        offs[i] = off;
        cursor[i] = off;
        dinv[i] = rsqrtf((float)(v + 1));
    }
    if (i == 0) offs[N] = E;
}

__global__ void scatter_kernel(const int* __restrict__ ei, int E, int* cursor, int* csr) {
    int e = blockIdx.x * blockDim.x + threadIdx.x;
    if (e >= E) return;
    int d = ei[E + e];
    int pos = atomicAdd(cursor + d, 1);
    csr[pos] = ei[e];
}

// ---------------- GAT aggregation: warp/node, branchless, fp16 gathers ----------------
__global__ __launch_bounds__(256) void gat_agg_kernel(const int* __restrict__ csr,
                                                      const int* __restrict__ offs,
                                                      const __half2* __restrict__ h,
                                                      const float* __restrict__ asrc,
                                                      const float* __restrict__ adst,
                                                      const float* __restrict__ b_gat,
                                                      const float* __restrict__ bn1w,
                                                      const float* __restrict__ bn1b,
                                                      float* __restrict__ out1, int N) {
    int n = (blockIdx.x * 256 + threadIdx.x) >> 5;
    if (n >= N) return;
    int lane = threadIdx.x & 31;
    int hd  = lane >> 3;
    int sub = lane & 7;
    int grp = lane & 24;
    int beg = offs[n], end = offs[n + 1];

    float adn = __ldg(adst + n * 4 + hd);
    float asn = __ldg(asrc + n * 4 + hd);
    float wself = __expf(lrelu(asn + adn));

    uint2 us = __ldg((const uint2*)(h + n * 64 + lane * 2));
    float2 h0 = __half22float2(*(__half2*)&us.x);
    float2 h1 = __half22float2(*(__half2*)&us.y);
    float4 acc = make_float4(h0.x * wself, h0.y * wself, h1.x * wself, h1.y * wself);

    float wpart = 0.f;
    for (int c0 = beg; c0 < end; c0 += 8) {
        int e = c0 + sub;
        float w = 0.f; int s = 0;
        if (e < end) {
            s = __ldg(csr + e);
            w = __expf(lrelu(__ldg(asrc + s * 4 + hd) + adn));
        }
        wpart += w;
        #pragma unroll
        for (int i = 0; i < 8; i++) {
            int   si = __shfl_sync(0xffffffffu, s, i);
            float a  = __shfl_sync(0xffffffffu, w, grp + i);
            uint2 u = __ldg((const uint2*)(h + si * 64 + lane * 2));
            float2 g0 = __half22float2(*(__half2*)&u.x);
            float2 g1 = __half22float2(*(__half2*)&u.y);
            acc.x += g0.x * a; acc.y += g0.y * a;
            acc.z += g1.x * a; acc.w += g1.y * a;
        }
    }

    #pragma unroll
    for (int o = 1; o < 8; o <<= 1) wpart += __shfl_xor_sync(0xffffffffu, wpart, o);
    float inv = 1.f / (wpart + wself + 1e-16f);

    int c = lane * 4;
    float4 bb = *(const float4*)(b_gat + c);
    float4 w1 = *(const float4*)(bn1w + c);
    float4 b1 = *(const float4*)(bn1b + c);
    float4 v;
    v.x = elu_f(acc.x * inv + bb.x) * w1.x + b1.x;
    v.y = elu_f(acc.y * inv + bb.y) * w1.y + b1.y;
    v.z = elu_f(acc.z * inv + bb.z) * w1.z + b1.z;
    v.w = elu_f(acc.w * inv + bb.w) * w1.w + b1.w;
    *(float4*)(out1 + n * 128 + c) = v;
}

// ---------------- GCN aggregation + gate + fused pooling: warp/node ----------------
__global__ __launch_bounds__(256) void gcn_agg_kernel(const int* __restrict__ csr,
                                                      const int* __restrict__ offs,
                                                      const __half2* __restrict__ h2,
                                                      const float* __restrict__ dinv,
                                                      const float* __restrict__ b_gcn,
                                                      const float* __restrict__ bn2w,
                                                      const float* __restrict__ bn2b,
                                                      const float* __restrict__ W_gate,
                                                      const float* __restrict__ b_gate,
                                                      const int* __restrict__ batch,
                                                      float* gacc, float* gsum, int N) {
    int n = (blockIdx.x * 256 + threadIdx.x) >> 5;
    if (n >= N) return;
    int lane = threadIdx.x & 31;
    int sub = lane & 7;
    int beg = offs[n], end = offs[n + 1];
    float dn = __ldg(dinv + n);

    uint2 us = __ldg((const uint2*)(h2 + n * 64 + lane * 2));
    float2 h0 = __half22float2(*(__half2*)&us.x);
    float2 h1 = __half22float2(*(__half2*)&us.y);
    float fs = dn * dn;
    float4 acc = make_float4(h0.x * fs, h0.y * fs, h1.x * fs, h1.y * fs);

    for (int c0 = beg; c0 < end; c0 += 8) {
        int e = c0 + sub;
        float f = 0.f; int s = 0;
        if (e < end) {
            s = __ldg(csr + e);
            f = __ldg(dinv + s) * dn;
        }
        #pragma unroll
        for (int i = 0; i < 8; i++) {
            int   si = __shfl_sync(0xffffffffu, s, i);
            float a  = __shfl_sync(0xffffffffu, f, i);
            uint2 u = __ldg((const uint2*)(h2 + si * 64 + lane * 2));
            float2 g0 = __half22float2(*(__half2*)&u.x);
            float2 g1 = __half22float2(*(__half2*)&u.y);
            acc.x += g0.x * a; acc.y += g0.y * a;
            acc.z += g1.x * a; acc.w += g1.y * a;
        }
    }

    int c = lane * 4;
    float4 bb = *(const float4*)(b_gcn + c);
    float4 w2 = *(const float4*)(bn2w + c);
    float4 b2 = *(const float4*)(bn2b + c);
    float4 v;
    v.x = elu_f(acc.x + bb.x) * w2.x + b2.x;
    v.y = elu_f(acc.y + bb.y) * w2.y + b2.y;
    v.z = elu_f(acc.z + bb.z) * w2.z + b2.z;
    v.w = elu_f(acc.w + bb.w) * w2.w + b2.w;

    // gate dot (full 128 cols within warp)
    float4 wg = *(const float4*)(W_gate + c);
    float p = v.x * wg.x + v.y * wg.y + v.z * wg.z + v.w * wg.w;
    #pragma unroll
    for (int o = 16; o; o >>= 1) p += __shfl_xor_sync(0xffffffffu, p, o);
    float gate = p + __ldg(b_gate);

    // fused global-attention pooling (softmax shift-invariant: no max subtraction)
    float wv = __expf(gate);
    int b = __ldg(batch + n);
    atomicAdd((float4*)(gacc + b * 128 + c),
              make_float4(v.x * wv, v.y * wv, v.z * wv, v.w * wv));
    if (lane == 0) atomicAdd(gsum + b, wv);
}

// ---------------- final: out[g] = ((gacc/gsum) . W_fc) + b_fc ----------------
__global__ __launch_bounds__(128) void final_kernel(const float* __restrict__ gacc,
                                                    const float* __restrict__ gsum,
                                                    const float* __restrict__ W_fc,
                                                    const float* __restrict__ b_fc,
                                                    float* __restrict__ out) {
    int g = blockIdx.x;
    int c = threadIdx.x;
    float v = gacc[g * 128 + c] / (gsum[g] + 1e-16f) * W_fc[c];
    #pragma unroll
    for (int o = 16; o; o >>= 1) v += __shfl_xor_sync(0xffffffffu, v, o);
    __shared__ float sr[4];
    if ((c & 31) == 0) sr[c >> 5] = v;
    __syncthreads();
    if (c == 0) out[g] = sr[0] + sr[1] + sr[2] + sr[3] + b_fc[0];
}

// ---------------- launch ----------------
extern "C" void kernel_launch(void* const* d_in, const int* in_sizes, int n_in,
                              void* d_out, int out_size) {
    const float* x       = (const float*)d_in[0];
    const int*   ei      = (const int*)d_in[1];
    const int*   batch   = (const int*)d_in[2];
    const float* W_gat   = (const float*)d_in[3];
    const float* att_src = (const float*)d_in[4];
    const float* att_dst = (const float*)d_in[5];
    const float* b_gat   = (const float*)d_in[6];
    const float* bn1w    = (const float*)d_in[7];
    const float* bn1b    = (const float*)d_in[8];
    const float* W_gcn   = (const float*)d_in[9];
    const float* b_gcn   = (const float*)d_in[10];
    const float* bn2w    = (const float*)d_in[11];
    const float* bn2b    = (const float*)d_in[12];
    const float* W_gate  = (const float*)d_in[13];
    const float* b_gate  = (const float*)d_in[14];
    const float* W_fc    = (const float*)d_in[15];
    const float* b_fc    = (const float*)d_in[16];
    float* out = (float*)d_out;

    int N = in_sizes[0] / 128;
    int E = in_sizes[1] / 2;
    int NB = (N + SCAN_B - 1) / SCAN_B;

    float *p_asrc, *p_adst, *p_out1, *p_dinv, *p_gacc, *p_gsum;
    __half2 *p_h, *p_h2;
    uint2 *p_wh1, *p_wl1, *p_wh2, *p_wl2;
    int *p_cnt, *p_offs, *p_cursor, *p_csr, *p_bsum, *p_boff;
    cudaGetSymbolAddress((void**)&p_h,     g_h);
    cudaGetSymbolAddress((void**)&p_h2,    g_h2);
    cudaGetSymbolAddress((void**)&p_asrc,  g_asrc);
    cudaGetSymbolAddress((void**)&p_adst,  g_adst);
    cudaGetSymbolAddress((void**)&p_out1,  g_out1);
    cudaGetSymbolAddress((void**)&p_dinv,  g_dinv);
    cudaGetSymbolAddress((void**)&p_cnt,   g_cnt);
    cudaGetSymbolAddress((void**)&p_offs,  g_offs);
    cudaGetSymbolAddress((void**)&p_cursor,g_cursor);
    cudaGetSymbolAddress((void**)&p_csr,   g_csr);
    cudaGetSymbolAddress((void**)&p_bsum,  g_bsum);
    cudaGetSymbolAddress((void**)&p_boff,  g_boff);
    cudaGetSymbolAddress((void**)&p_gacc,  g_gacc);
    cudaGetSymbolAddress((void**)&p_gsum,  g_gsum);
    cudaGetSymbolAddress((void**)&p_wh1,   g_wh1);
    cudaGetSymbolAddress((void**)&p_wl1,   g_wl1);
    cudaGetSymbolAddress((void**)&p_wh2,   g_wh2);
    cudaGetSymbolAddress((void**)&p_wl2,   g_wl2);

    int gblk = (N + 63) / 64;
    int ablk = (N * 32 + 255) / 256;   // warp per node

    init_kernel<<<(N + 255) / 256, 256>>>(p_cnt, p_gacc, p_gsum, N);                // 0
    hist_kernel<<<(E + 255) / 256, 256>>>(ei, E, p_cnt);                            // 1
    wpack_kernel<<<32, 256>>>(W_gat, W_gcn, p_wh1, p_wl1, p_wh2, p_wl2);            // 2
    gemm_tc_kernel<true><<<gblk, 256>>>(x, p_wh1, p_wl1, p_h, att_src, att_dst,
                                        p_asrc, p_adst, N);                         // 3 (ncu)
    blocksum_kernel<<<NB, SCAN_B>>>(p_cnt, p_bsum, N);                              // 4
    bscan_kernel<<<1, 256>>>(p_bsum, p_boff, NB);                                   // 5
    scanfin_kernel<<<NB, SCAN_B>>>(p_cnt, p_boff, p_offs, p_cursor, p_dinv, N, E);  // 6
    scatter_kernel<<<(E + 255) / 256, 256>>>(ei, E, p_cursor, p_csr);               // 7
    gat_agg_kernel<<<ablk, 256>>>(p_csr, p_offs, p_h, p_asrc, p_adst,
                                  b_gat, bn1w, bn1b, p_out1, N);                    // 8
    gemm_tc_kernel<false><<<gblk, 256>>>(p_out1, p_wh2, p_wl2, p_h2, nullptr, nullptr,
                                         nullptr, nullptr, N);                      // 9
    gcn_agg_kernel<<<ablk, 256>>>(p_csr, p_offs, p_h2, p_dinv,
                                  b_gcn, bn2w, bn2b, W_gate, b_gate, batch,
                                  p_gacc, p_gsum, N);                               // 10
    final_kernel<<<64, 128>>>(p_gacc, p_gsum, W_fc, b_fc, out);                     // 11
}

// round 16
// speedup vs baseline: 1.3773x; 1.3773x over previous
#include <cuda_runtime.h>
#include <cuda_bf16.h>
#include <cuda_fp16.h>
#include <math.h>

#define NMAX 50048
#define EMAX 800000
#define SCAN_B 256

// ---------------- scratch (device globals) ----------------
__device__ __half2 g_h[NMAX * 64];     // x @ W_gat (fp16 messages)
__device__ __half2 g_h2[NMAX * 64];    // out1 @ W_gcn (fp16 messages)
__device__ float g_asrc[NMAX * 4];
__device__ float g_adst[NMAX * 4];
__device__ float g_out1[NMAX * 128];
__device__ float g_dinv[NMAX];
__device__ int   g_cnt[NMAX];
__device__ int   g_offs[NMAX + 1];
__device__ int   g_cursor[NMAX];
__device__ int   g_csr[EMAX];
__device__ int   g_bsum[(NMAX + SCAN_B - 1) / SCAN_B];
__device__ int   g_boff[(NMAX + SCAN_B - 1) / SCAN_B];
__device__ float g_gacc[64 * 128];
__device__ float g_gsum[64];
// packed bf16 hi/lo weights, fragment order: [slab8][col128][kq4] uint2
__device__ uint2 g_wh1[4096];
__device__ uint2 g_wl1[4096];
__device__ uint2 g_wh2[4096];
__device__ uint2 g_wl2[4096];

// ---------------- helpers ----------------
__device__ __forceinline__ float lrelu(float v) { return v > 0.f ? v : 0.2f * v; }
__device__ __forceinline__ float elu_f(float v) { return v > 0.f ? v : (__expf(v) - 1.f); }

__device__ __forceinline__ void split_bf(float x, float y, unsigned& hi, unsigned& lo) {
    __nv_bfloat162 h = __floats2bfloat162_rn(x, y);
    float rx = x - __bfloat162float(h.x);
    float ry = y - __bfloat162float(h.y);
    __nv_bfloat162 l = __floats2bfloat162_rn(rx, ry);
    hi = *(unsigned*)&h;
    lo = *(unsigned*)&l;
}

__device__ __forceinline__ void mma_bf16(float* d, const unsigned* a, unsigned b0, unsigned b1) {
    asm("mma.sync.aligned.m16n8k16.row.col.f32.bf16.bf16.f32 "
        "{%0,%1,%2,%3},{%4,%5,%6,%7},{%8,%9},{%0,%1,%2,%3};"
        : "+f"(d[0]), "+f"(d[1]), "+f"(d[2]), "+f"(d[3])
        : "r"(a[0]), "r"(a[1]), "r"(a[2]), "r"(a[3]), "r"(b0), "r"(b1));
}

// ---------------- init ----------------
__global__ void init_kernel(int* cnt, float* gacc, float* gsum, int N) {
    int i = blockIdx.x * blockDim.x + threadIdx.x;
    if (i < N) cnt[i] = 0;
    if (i < 64 * 128) gacc[i] = 0.f;
    if (i < 64) gsum[i] = 0.f;
}

// ---------------- CSR: histogram ----------------
__global__ void hist_kernel(const int* __restrict__ ei, int E, int* cnt) {
    int e = blockIdx.x * blockDim.x + threadIdx.x;
    if (e >= E) return;
    atomicAdd(cnt + ei[E + e], 1);
}

// ---------------- pack BOTH weight matrices into bf16 hi/lo fragment order ----------------
__global__ void wpack_kernel(const float* __restrict__ W1, const float* __restrict__ W2,
                             uint2* Wh1, uint2* Wl1, uint2* Wh2, uint2* Wl2) {
    int t = blockIdx.x * blockDim.x + threadIdx.x;
    if (t >= 8192) return;
    const float* W = (t < 4096) ? W1 : W2;
    uint2* Wh = (t < 4096) ? Wh1 : Wh2;
    uint2* Wl = (t < 4096) ? Wl1 : Wl2;
    int i = t & 4095;
    int kq   = i & 3;
    int col  = (i >> 2) & 127;
    int slab = i >> 9;
    int k0 = slab * 16 + 2 * kq;
    uint2 h, l;
    split_bf(W[k0 * 128 + col],       W[(k0 + 1) * 128 + col], h.x, l.x);
    split_bf(W[(k0 + 8) * 128 + col], W[(k0 + 9) * 128 + col], h.y, l.y);
    Wh[i] = h;
    Wl[i] = l;
}

// ---------------- tensor-core GEMM: Ch[N,128](fp16) = A[N,128] @ W[128,128], 3xBF16 ----------------
template <bool ATTN>
__global__ __launch_bounds__(256, 2) void gemm_tc_kernel(const float* __restrict__ A,
                                                         const uint2* __restrict__ Wh,
                                                         const uint2* __restrict__ Wl,
                                                         __half2* __restrict__ Ch,
                                                         const float* __restrict__ att_src,
                                                         const float* __restrict__ att_dst,
                                                         float* __restrict__ asrc,
                                                         float* __restrict__ adst, int N) {
    __shared__ float As[2][64 * 36];
    __shared__ uint2 Bh[2][1024];
    __shared__ uint2 Bl[2][1024];

    int t = threadIdx.x;
    int warp = t >> 5, lane = t & 31;
    int g4 = lane >> 2, kq = lane & 3;
    int rg = warp >> 1;
    int ch = warp & 1;
    int wrow = rg * 16;
    int brow0 = blockIdx.x * 64;

    int arow0 = t >> 3, ac4 = t & 7;
    int arow1 = (t + 256) >> 3;

    float acc[8][4];
    #pragma unroll
    for (int j = 0; j < 8; j++)
        #pragma unroll
        for (int q = 0; q < 4; q++) acc[j][q] = 0.f;

    {
        float4 va0 = make_float4(0.f, 0.f, 0.f, 0.f);
        float4 va1 = make_float4(0.f, 0.f, 0.f, 0.f);
        if (brow0 + arow0 < N) va0 = ((const float4*)A)[(brow0 + arow0) * 32 + ac4];
        if (brow0 + arow1 < N) va1 = ((const float4*)A)[(brow0 + arow1) * 32 + ac4];
        float4 vh0 = ((const float4*)Wh)[t];
        float4 vh1 = ((const float4*)Wh)[t + 256];
        float4 vl0 = ((const float4*)Wl)[t];
        float4 vl1 = ((const float4*)Wl)[t + 256];
        *(float4*)(As[0] + arow0 * 36 + ac4 * 4) = va0;
        *(float4*)(As[0] + arow1 * 36 + ac4 * 4) = va1;
        ((float4*)Bh[0])[t] = vh0;
        ((float4*)Bh[0])[t + 256] = vh1;
        ((float4*)Bl[0])[t] = vl0;
        ((float4*)Bl[0])[t + 256] = vl1;
    }
    __syncthreads();

    #pragma unroll
    for (int stage = 0; stage < 4; stage++) {
        int cur = stage & 1, nxt = cur ^ 1;

        float4 va0, va1, vh0, vh1, vl0, vl1;
        if (stage < 3) {
            int s1 = stage + 1;
            va0 = make_float4(0.f, 0.f, 0.f, 0.f);
            va1 = make_float4(0.f, 0.f, 0.f, 0.f);
            if (brow0 + arow0 < N) va0 = ((const float4*)A)[(brow0 + arow0) * 32 + s1 * 8 + ac4];
            if (brow0 + arow1 < N) va1 = ((const float4*)A)[(brow0 + arow1) * 32 + s1 * 8 + ac4];
            vh0 = ((const float4*)Wh)[s1 * 512 + t];
            vh1 = ((const float4*)Wh)[s1 * 512 + t + 256];
            vl0 = ((const float4*)Wl)[s1 * 512 + t];
            vl1 = ((const float4*)Wl)[s1 * 512 + t + 256];
        }

        #pragma unroll
        for (int sl = 0; sl < 2; sl++) {
            int kb = sl * 16 + 2 * kq;
            float2 A0 = *(const float2*)(As[cur] + (wrow + g4) * 36 + kb);
            float2 A1 = *(const float2*)(As[cur] + (wrow + g4) * 36 + kb + 8);
            float2 A2 = *(const float2*)(As[cur] + (wrow + g4 + 8) * 36 + kb);
            float2 A3 = *(const float2*)(As[cur] + (wrow + g4 + 8) * 36 + kb + 8);
            unsigned ah[4], al[4];
            split_bf(A0.x, A0.y, ah[0], al[0]);
            split_bf(A2.x, A2.y, ah[1], al[1]);
            split_bf(A1.x, A1.y, ah[2], al[2]);
            split_bf(A3.x, A3.y, ah[3], al[3]);
            #pragma unroll
            for (int j = 0; j < 8; j++) {
                int ct = ch * 8 + j;
                uint2 bh = Bh[cur][sl * 512 + (ct * 8 + g4) * 4 + kq];
                uint2 bl = Bl[cur][sl * 512 + (ct * 8 + g4) * 4 + kq];
                mma_bf16(acc[j], ah, bh.x, bh.y);
                mma_bf16(acc[j], al, bh.x, bh.y);
                mma_bf16(acc[j], ah, bl.x, bl.y);
            }
        }

        if (stage < 3) {
            *(float4*)(As[nxt] + arow0 * 36 + ac4 * 4) = va0;
            *(float4*)(As[nxt] + arow1 * 36 + ac4 * 4) = va1;
            ((float4*)Bh[nxt])[t] = vh0;
            ((float4*)Bh[nxt])[t + 256] = vh1;
            ((float4*)Bl[nxt])[t] = vl0;
            ((float4*)Bl[nxt])[t + 256] = vl1;
            __syncthreads();
        }
    }

    int r0 = brow0 + wrow + g4;
    #pragma unroll
    for (int j = 0; j < 8; j++) {
        int hcol = ch * 32 + j * 4 + kq;
        if (r0 < N)
            Ch[r0 * 64 + hcol] = __floats2half2_rn(acc[j][0], acc[j][1]);
        if (r0 + 8 < N)
            Ch[(r0 + 8) * 64 + hcol] = __floats2half2_rn(acc[j][2], acc[j][3]);
    }

    if (ATTN) {
        #pragma unroll
        for (int hh = 0; hh < 2; hh++) {
            int head = ch * 2 + hh;
            float psl = 0.f, psh = 0.f, pdl = 0.f, pdh = 0.f;
            #pragma unroll
            for (int jj = 0; jj < 4; jj++) {
                int j = hh * 4 + jj;
                int col = ch * 64 + j * 8 + 2 * kq;
                float2 av = *(const float2*)(att_src + col);
                float2 dv = *(const float2*)(att_dst + col);
                psl += acc[j][0] * av.x + acc[j][1] * av.y;
                psh += acc[j][2] * av.x + acc[j][3] * av.y;
                pdl += acc[j][0] * dv.x + acc[j][1] * dv.y;
                pdh += acc[j][2] * dv.x + acc[j][3] * dv.y;
            }
            psl += __shfl_xor_sync(0xffffffffu, psl, 1);
            psl += __shfl_xor_sync(0xffffffffu, psl, 2);
            psh += __shfl_xor_sync(0xffffffffu, psh, 1);
            psh += __shfl_xor_sync(0xffffffffu, psh, 2);
            pdl += __shfl_xor_sync(0xffffffffu, pdl, 1);
            pdl += __shfl_xor_sync(0xffffffffu, pdl, 2);
            pdh += __shfl_xor_sync(0xffffffffu, pdh, 1);
            pdh += __shfl_xor_sync(0xffffffffu, pdh, 2);
            if (kq == 0) {
                if (r0 < N)     { asrc[r0 * 4 + head] = psl;       adst[r0 * 4 + head] = pdl; }
                if (r0 + 8 < N) { asrc[(r0 + 8) * 4 + head] = psh; adst[(r0 + 8) * 4 + head] = pdh; }
            }
        }
    }
}

// ---------------- CSR scan ----------------
__global__ __launch_bounds__(SCAN_B) void blocksum_kernel(const int* __restrict__ cnt,
                                                          int* bsum, int N) {
    __shared__ int sh[SCAN_B];
    int i = blockIdx.x * SCAN_B + threadIdx.x;
    sh[threadIdx.x] = (i < N) ? cnt[i] : 0;
    __syncthreads();
    #pragma unroll
    for (int o = SCAN_B / 2; o; o >>= 1) {
        if (threadIdx.x < o) sh[threadIdx.x] += sh[threadIdx.x + o];
        __syncthreads();
    }
    if (threadIdx.x == 0) bsum[blockIdx.x] = sh[0];
}

__global__ __launch_bounds__(256) void bscan_kernel(const int* __restrict__ bsum,
                                                    int* boff, int NB) {
    __shared__ int sh[256];
    int t = threadIdx.x;
    sh[t] = (t < NB) ? bsum[t] : 0;
    __syncthreads();
    #pragma unroll
    for (int o = 1; o < 256; o <<= 1) {
        int v = (t >= o) ? sh[t - o] : 0;
        __syncthreads();
        sh[t] += v;
        __syncthreads();
    }
    if (t < NB) boff[t] = (t == 0) ? 0 : sh[t - 1];
}

// scanfin also emits dinv (deg = cnt + 1 self loop)
__global__ __launch_bounds__(SCAN_B) void scanfin_kernel(const int* __restrict__ cnt,
                                                         const int* __restrict__ boff,
                                                         int* offs, int* cursor,
                                                         float* dinv, int N, int E) {
    __shared__ int sh[SCAN_B];
    int t = threadIdx.x;
    int i = blockIdx.x * SCAN_B + t;
    int v = (i < N) ? cnt[i] : 0;
    sh[t] = v;
    __syncthreads();
    #pragma unroll
    for (int o = 1; o < SCAN_B; o <<= 1) {
        int u = (t >= o) ? sh[t - o] : 0;
        __syncthreads();
        sh[t] += u;
        __syncthreads();
    }
    if (i < N) {
        int off = boff[blockIdx.x] + sh[t] - v;
        offs[i] = off;
        cursor[i] = off;
        dinv[i] = rsqrtf((float)(v + 1));
    }
    if (i == 0) offs[N] = E;
}

__global__ void scatter_kernel(const int* __restrict__ ei, int E, int* cursor, int* csr) {
    int e = blockIdx.x * blockDim.x + threadIdx.x;
    if (e >= E) return;
    int d = ei[E + e];
    int pos = atomicAdd(cursor + d, 1);
    csr[pos] = ei[e];
}

// ---------------- GAT aggregation: warp/node, branchless, fp16 gathers ----------------
__global__ __launch_bounds__(256) void gat_agg_kernel(const int* __restrict__ csr,
                                                      const int* __restrict__ offs,
                                                      const __half2* __restrict__ h,
                                                      const float* __restrict__ asrc,
                                                      const float* __restrict__ adst,
                                                      const float* __restrict__ b_gat,
                                                      const float* __restrict__ bn1w,
                                                      const float* __restrict__ bn1b,
                                                      float* __restrict__ out1, int N) {
    int n = (blockIdx.x * 256 + threadIdx.x) >> 5;
    if (n >= N) return;
    int lane = threadIdx.x & 31;
    int hd  = lane >> 3;
    int sub = lane & 7;
    int grp = lane & 24;
    int beg = offs[n], end = offs[n + 1];

    float adn = __ldg(adst + n * 4 + hd);
    float asn = __ldg(asrc + n * 4 + hd);
    float wself = __expf(lrelu(asn + adn));

    uint2 us = __ldg((const uint2*)(h + n * 64 + lane * 2));
    float2 h0 = __half22float2(*(__half2*)&us.x);
    float2 h1 = __half22float2(*(__half2*)&us.y);
    float4 acc = make_float4(h0.x * wself, h0.y * wself, h1.x * wself, h1.y * wself);

    float wpart = 0.f;
    for (int c0 = beg; c0 < end; c0 += 8) {
        int e = c0 + sub;
        float w = 0.f; int s = 0;
        if (e < end) {
            s = __ldg(csr + e);
            w = __expf(lrelu(__ldg(asrc + s * 4 + hd) + adn));
        }
        wpart += w;
        #pragma unroll
        for (int i = 0; i < 8; i++) {
            int   si = __shfl_sync(0xffffffffu, s, i);
            float a  = __shfl_sync(0xffffffffu, w, grp + i);
            uint2 u = __ldg((const uint2*)(h + si * 64 + lane * 2));
            float2 g0 = __half22float2(*(__half2*)&u.x);
            float2 g1 = __half22float2(*(__half2*)&u.y);
            acc.x += g0.x * a; acc.y += g0.y * a;
            acc.z += g1.x * a; acc.w += g1.y * a;
        }
    }

    #pragma unroll
    for (int o = 1; o < 8; o <<= 1) wpart += __shfl_xor_sync(0xffffffffu, wpart, o);
    float inv = 1.f / (wpart + wself + 1e-16f);

    int c = lane * 4;
    float4 bb = *(const float4*)(b_gat + c);
    float4 w1 = *(const float4*)(bn1w + c);
    float4 b1 = *(const float4*)(bn1b + c);
    float4 v;
    v.x = elu_f(acc.x * inv + bb.x) * w1.x + b1.x;
    v.y = elu_f(acc.y * inv + bb.y) * w1.y + b1.y;
    v.z = elu_f(acc.z * inv + bb.z) * w1.z + b1.z;
    v.w = elu_f(acc.w * inv + bb.w) * w1.w + b1.w;
    *(float4*)(out1 + n * 128 + c) = v;
}

// ---------------- GCN aggregation + gate + fused pooling: warp/node ----------------
__global__ __launch_bounds__(256) void gcn_agg_kernel(const int* __restrict__ csr,
                                                      const int* __restrict__ offs,
                                                      const __half2* __restrict__ h2,
                                                      const float* __restrict__ dinv,
                                                      const float* __restrict__ b_gcn,
                                                      const float* __restrict__ bn2w,
                                                      const float* __restrict__ bn2b,
                                                      const float* __restrict__ W_gate,
                                                      const float* __restrict__ b_gate,
                                                      const int* __restrict__ batch,
                                                      float* gacc, float* gsum, int N) {
    int n = (blockIdx.x * 256 + threadIdx.x) >> 5;
    if (n >= N) return;
    int lane = threadIdx.x & 31;
    int sub = lane & 7;
    int beg = offs[n], end = offs[n + 1];
    float dn = __ldg(dinv + n);

    uint2 us = __ldg((const uint2*)(h2 + n * 64 + lane * 2));
    float2 h0 = __half22float2(*(__half2*)&us.x);
    float2 h1 = __half22float2(*(__half2*)&us.y);
    float fs = dn * dn;
    float4 acc = make_float4(h0.x * fs, h0.y * fs, h1.x * fs, h1.y * fs);

    for (int c0 = beg; c0 < end; c0 += 8) {
        int e = c0 + sub;
        float f = 0.f; int s = 0;
        if (e < end) {
            s = __ldg(csr + e);
            f = __ldg(dinv + s) * dn;
        }
        #pragma unroll
        for (int i = 0; i < 8; i++) {
            int   si = __shfl_sync(0xffffffffu, s, i);
            float a  = __shfl_sync(0xffffffffu, f, i);
            uint2 u = __ldg((const uint2*)(h2 + si * 64 + lane * 2));
            float2 g0 = __half22float2(*(__half2*)&u.x);
            float2 g1 = __half22float2(*(__half2*)&u.y);
            acc.x += g0.x * a; acc.y += g0.y * a;
            acc.z += g1.x * a; acc.w += g1.y * a;
        }
    }

    int c = lane * 4;
    float4 bb = *(const float4*)(b_gcn + c);
    float4 w2 = *(const float4*)(bn2w + c);
    float4 b2 = *(const float4*)(bn2b + c);
    float4 v;
    v.x = elu_f(acc.x + bb.x) * w2.x + b2.x;
    v.y = elu_f(acc.y + bb.y) * w2.y + b2.y;
    v.z = elu_f(acc.z + bb.z) * w2.z + b2.z;
    v.w = elu_f(acc.w + bb.w) * w2.w + b2.w;

    // gate dot (full 128 cols within warp)
    float4 wg = *(const float4*)(W_gate + c);
    float p = v.x * wg.x + v.y * wg.y + v.z * wg.z + v.w * wg.w;
    #pragma unroll
    for (int o = 16; o; o >>= 1) p += __shfl_xor_sync(0xffffffffu, p, o);
    float gate = p + __ldg(b_gate);

    // fused global-attention pooling (softmax shift-invariant: no max subtraction)
    float wv = __expf(gate);
    int b = __ldg(batch + n);
    atomicAdd((float4*)(gacc + b * 128 + c),
              make_float4(v.x * wv, v.y * wv, v.z * wv, v.w * wv));
    if (lane == 0) atomicAdd(gsum + b, wv);
}

// ---------------- final: out[g] = ((gacc/gsum) . W_fc) + b_fc ----------------
__global__ __launch_bounds__(128) void final_kernel(const float* __restrict__ gacc,
                                                    const float* __restrict__ gsum,
                                                    const float* __restrict__ W_fc,
                                                    const float* __restrict__ b_fc,
                                                    float* __restrict__ out) {
    int g = blockIdx.x;
    int c = threadIdx.x;
    float v = gacc[g * 128 + c] / (gsum[g] + 1e-16f) * W_fc[c];
    #pragma unroll
    for (int o = 16; o; o >>= 1) v += __shfl_xor_sync(0xffffffffu, v, o);
    __shared__ float sr[4];
    if ((c & 31) == 0) sr[c >> 5] = v;
    __syncthreads();
    if (c == 0) out[g] = sr[0] + sr[1] + sr[2] + sr[3] + b_fc[0];
}

// ---------------- launch ----------------
extern "C" void kernel_launch(void* const* d_in, const int* in_sizes, int n_in,
                              void* d_out, int out_size) {
    const float* x       = (const float*)d_in[0];
    const int*   ei      = (const int*)d_in[1];
    const int*   batch   = (const int*)d_in[2];
    const float* W_gat   = (const float*)d_in[3];
    const float* att_src = (const float*)d_in[4];
    const float* att_dst = (const float*)d_in[5];
    const float* b_gat   = (const float*)d_in[6];
    const float* bn1w    = (const float*)d_in[7];
    const float* bn1b    = (const float*)d_in[8];
    const float* W_gcn   = (const float*)d_in[9];
    const float* b_gcn   = (const float*)d_in[10];
    const float* bn2w    = (const float*)d_in[11];
    const float* bn2b    = (const float*)d_in[12];
    const float* W_gate  = (const float*)d_in[13];
    const float* b_gate  = (const float*)d_in[14];
    const float* W_fc    = (const float*)d_in[15];
    const float* b_fc    = (const float*)d_in[16];
    float* out = (float*)d_out;

    int N = in_sizes[0] / 128;
    int E = in_sizes[1] / 2;
    int NB = (N + SCAN_B - 1) / SCAN_B;

    float *p_asrc, *p_adst, *p_out1, *p_dinv, *p_gacc, *p_gsum;
    __half2 *p_h, *p_h2;
    uint2 *p_wh1, *p_wl1, *p_wh2, *p_wl2;
    int *p_cnt, *p_offs, *p_cursor, *p_csr, *p_bsum, *p_boff;
    cudaGetSymbolAddress((void**)&p_h,     g_h);
    cudaGetSymbolAddress((void**)&p_h2,    g_h2);
    cudaGetSymbolAddress((void**)&p_asrc,  g_asrc);
    cudaGetSymbolAddress((void**)&p_adst,  g_adst);
    cudaGetSymbolAddress((void**)&p_out1,  g_out1);
    cudaGetSymbolAddress((void**)&p_dinv,  g_dinv);
    cudaGetSymbolAddress((void**)&p_cnt,   g_cnt);
    cudaGetSymbolAddress((void**)&p_offs,  g_offs);
    cudaGetSymbolAddress((void**)&p_cursor,g_cursor);
    cudaGetSymbolAddress((void**)&p_csr,   g_csr);
    cudaGetSymbolAddress((void**)&p_bsum,  g_bsum);
    cudaGetSymbolAddress((void**)&p_boff,  g_boff);
    cudaGetSymbolAddress((void**)&p_gacc,  g_gacc);
    cudaGetSymbolAddress((void**)&p_gsum,  g_gsum);
    cudaGetSymbolAddress((void**)&p_wh1,   g_wh1);
    cudaGetSymbolAddress((void**)&p_wl1,   g_wl1);
    cudaGetSymbolAddress((void**)&p_wh2,   g_wh2);
    cudaGetSymbolAddress((void**)&p_wl2,   g_wl2);

    int gblk = (N + 63) / 64;
    int ablk = (N * 32 + 255) / 256;   // warp per node

    init_kernel<<<(N + 255) / 256, 256>>>(p_cnt, p_gacc, p_gsum, N);                // 0
    hist_kernel<<<(E + 255) / 256, 256>>>(ei, E, p_cnt);                            // 1
    wpack_kernel<<<32, 256>>>(W_gat, W_gcn, p_wh1, p_wl1, p_wh2, p_wl2);            // 2
    gemm_tc_kernel<true><<<gblk, 256>>>(x, p_wh1, p_wl1, p_h, att_src, att_dst,
                                        p_asrc, p_adst, N);                         // 3 (ncu)
    blocksum_kernel<<<NB, SCAN_B>>>(p_cnt, p_bsum, N);                              // 4
    bscan_kernel<<<1, 256>>>(p_bsum, p_boff, NB);                                   // 5
    scanfin_kernel<<<NB, SCAN_B>>>(p_cnt, p_boff, p_offs, p_cursor, p_dinv, N, E);  // 6
    scatter_kernel<<<(E + 255) / 256, 256>>>(ei, E, p_cursor, p_csr);               // 7
    gat_agg_kernel<<<ablk, 256>>>(p_csr, p_offs, p_h, p_asrc, p_adst,
                                  b_gat, bn1w, bn1b, p_out1, N);                    // 8
    gemm_tc_kernel<false><<<gblk, 256>>>(p_out1, p_wh2, p_wl2, p_h2, nullptr, nullptr,
                                         nullptr, nullptr, N);                      // 9
    gcn_agg_kernel<<<ablk, 256>>>(p_csr, p_offs, p_h2, p_dinv,
                                  b_gcn, bn2w, bn2b, W_gate, b_gate, batch,
                                  p_gacc, p_gsum, N);                               // 10
    final_kernel<<<64, 128>>>(p_gacc, p_gsum, W_fc, b_fc, out);                     // 11
}